// round 9
// baseline (speedup 1.0000x reference)
#include <cuda_runtime.h>
#include <cuda_bf16.h>
#include <cstdint>

#define N_NODES 100000
#define N_EDGES 1600000
#define D 128
#define N_LAYERS 4
#define ROWU32 128          // 256 bf16 per activation row = 128 uint32

// ---------------- scratch (__device__ globals; no allocation) ----------------
__device__ float g_bufA[N_NODES * D];
__device__ float g_bufB[N_NODES * D];
__device__ float g_invdeg[N_NODES];
__device__ int   g_deg[N_NODES];
__device__ int   g_cursor[N_NODES];
__device__ int   g_rowstart[N_NODES + 1];
__device__ int   g_csr_src[N_EDGES];
// Packed bf16 activations [row][k2 permuted]: k2<64 = agg-half, >=64 = x-half
__device__ uint32_t g_Ahi[(size_t)N_NODES * ROWU32];
__device__ uint32_t g_Alo[(size_t)N_NODES * ROWU32];
// Packed bf16 weights [l][j][k2 permuted] (k<128 -> Wl, k>=128 -> Wr)
__device__ uint32_t g_Whi[N_LAYERS * D * ROWU32];
__device__ uint32_t g_Wlo[N_LAYERS * D * ROWU32];

// ------------------------------ helpers -------------------------------------
__device__ __forceinline__ uint32_t smem_u32(const void* p) {
    uint32_t a;
    asm("{ .reg .u64 t; cvta.to.shared.u64 t, %1; cvt.u32.u64 %0, t; }"
        : "=r"(a) : "l"(p));
    return a;
}
__device__ __forceinline__ void cp16(uint32_t saddr, const void* g) {
    asm volatile("cp.async.ca.shared.global [%0], [%1], 16;"
                 :: "r"(saddr), "l"(g) : "memory");
}
#define CP_COMMIT() asm volatile("cp.async.commit_group;" ::: "memory")
#define CP_WAIT(n)  asm volatile("cp.async.wait_group %0;" :: "n"(n) : "memory")

__device__ __forceinline__ uint32_t pack_bf16(__nv_bfloat16 a, __nv_bfloat16 b) {
    return ((uint32_t)__bfloat16_as_ushort(b) << 16) | (uint32_t)__bfloat16_as_ushort(a);
}
__device__ __forceinline__ void split_bf16(float x, __nv_bfloat16& h, __nv_bfloat16& l) {
    h = __float2bfloat16(x);
    l = __float2bfloat16(x - __bfloat162float(h));
}
// column permutation: within each 16-k2 chunk, pairs (c, c+4) become adjacent
__device__ __forceinline__ int permk2(int k2) {
    int c = k2 & 15;
    return (k2 & ~15) | ((c & 3) << 1) | ((c >> 2) & 1) | (c & 8);
}

__device__ __forceinline__ void mma_bf16(float c[4], const uint32_t a[4],
                                         uint32_t b0, uint32_t b1) {
    asm volatile(
        "mma.sync.aligned.m16n8k16.row.col.f32.bf16.bf16.f32 "
        "{%0,%1,%2,%3}, {%4,%5,%6,%7}, {%8,%9}, {%0,%1,%2,%3};"
        : "+f"(c[0]), "+f"(c[1]), "+f"(c[2]), "+f"(c[3])
        : "r"(a[0]), "r"(a[1]), "r"(a[2]), "r"(a[3]), "r"(b0), "r"(b1));
}

// ---------------------------------------------------------------------------
// Setup kernels. Launch order (all real kernels, no memset):
//   zero(1) deg(2) scan(3) fill(4) gather(5) gemm(6) <- profiled slot
// ---------------------------------------------------------------------------
__global__ void zero_kernel(int* __restrict__ deg) {
    int i = blockIdx.x * blockDim.x + threadIdx.x;
    if (i < N_NODES) deg[i] = 0;
}

__global__ void deg_kernel(const int* __restrict__ dst, int* __restrict__ deg) {
    int e = blockIdx.x * blockDim.x + threadIdx.x;
    if (e < N_EDGES) atomicAdd(&deg[dst[e]], 1);
}

__global__ void scan_kernel(const int* __restrict__ deg,
                            int* __restrict__ row_start,
                            float* __restrict__ invdeg,
                            int* __restrict__ cursor) {
    __shared__ int sm[1024];
    const int t = threadIdx.x;
    const int CH = (N_NODES + 1023) / 1024;
    const int base = t * CH;
    int s = 0;
    for (int i = 0; i < CH; i++) {
        int idx = base + i;
        if (idx < N_NODES) s += deg[idx];
    }
    sm[t] = s;
    __syncthreads();
    for (int d = 1; d < 1024; d <<= 1) {
        int v = (t >= d) ? sm[t - d] : 0;
        __syncthreads();
        sm[t] += v;
        __syncthreads();
    }
    int off = sm[t] - s;
    for (int i = 0; i < CH; i++) {
        int idx = base + i;
        if (idx < N_NODES) {
            row_start[idx] = off;
            int dg = deg[idx];
            off += dg;
            invdeg[idx] = 1.0f / fmaxf((float)dg, 1.0f);
            cursor[idx] = 0;
        }
    }
    if (t == 1023) row_start[N_NODES] = off;
}

// fill: CSR fill + W split (65536 thr) + layer-0 x-half split (6.4M thr)
__global__ void fill_kernel(const int* __restrict__ src,
                            const int* __restrict__ dst,
                            const int* __restrict__ row_start,
                            int* __restrict__ cursor,
                            int* __restrict__ csr_src,
                            const float* __restrict__ Wl,
                            const float* __restrict__ Wr,
                            const float* __restrict__ x,
                            uint32_t* __restrict__ Whi,
                            uint32_t* __restrict__ Wlo,
                            uint32_t* __restrict__ Ahi,
                            uint32_t* __restrict__ Alo) {
    int e = blockIdx.x * blockDim.x + threadIdx.x;
    if (e < N_EDGES) {
        int d = dst[e];
        int p = atomicAdd(&cursor[d], 1);
        csr_src[row_start[d] + p] = src[e];
    }
    if (e < N_LAYERS * D * ROWU32) {       // W hi/lo split (permuted cols)
        int k2 = e & (ROWU32 - 1);
        int j  = (e >> 7) & (D - 1);
        int l  = e >> 14;
        int k0 = 2 * k2, k1 = 2 * k2 + 1;
        float w0 = (k0 < D) ? Wl[(l * D + j) * D + k0] : Wr[(l * D + j) * D + (k0 - D)];
        float w1 = (k1 < D) ? Wl[(l * D + j) * D + k1] : Wr[(l * D + j) * D + (k1 - D)];
        __nv_bfloat16 h0, l0, h1, l1;
        split_bf16(w0, h0, l0);
        split_bf16(w1, h1, l1);
        int idx = (l * D + j) * ROWU32 + permk2(k2);
        Whi[idx] = pack_bf16(h0, h1);
        Wlo[idx] = pack_bf16(l0, l1);
    }
    if (e < N_NODES * 64) {                // layer-0 x-half split
        int row = e >> 6;
        int k2l = e & 63;
        float v0 = x[row * D + 2 * k2l];
        float v1 = x[row * D + 2 * k2l + 1];
        __nv_bfloat16 h0, l0, h1, l1;
        split_bf16(v0, h0, l0);
        split_bf16(v1, h1, l1);
        int idx = row * ROWU32 + permk2(64 + k2l);
        Ahi[idx] = pack_bf16(h0, h1);
        Alo[idx] = pack_bf16(l0, l1);
    }
}

// ---------------------------------------------------------------------------
// Gather-mean -> packed bf16 hi/lo agg-half (permuted cols). One warp/node,
// lane owns one float4 column chunk; 4-deep load ILP against L2 latency.
// ---------------------------------------------------------------------------
__global__ __launch_bounds__(256)
void gather_kernel(const float4* __restrict__ x4,
                   const int* __restrict__ csr_src,
                   const int* __restrict__ row_start,
                   const float* __restrict__ invdeg,
                   uint32_t* __restrict__ Ahi,
                   uint32_t* __restrict__ Alo) {
    int warp = (blockIdx.x * blockDim.x + threadIdx.x) >> 5;
    int lane = threadIdx.x & 31;
    if (warp >= N_NODES) return;
    int b = row_start[warp];
    int e = row_start[warp + 1];
    float4 a0 = make_float4(0.f, 0.f, 0.f, 0.f);
    float4 a1 = a0, a2 = a0, a3 = a0;
    for (int j = b; j < e; j += 32) {
        int cnt = min(32, e - j);
        int sreg = (lane < cnt) ? csr_src[j + lane] : 0;
        int i = 0;
        int i4 = cnt & ~3;
        for (; i < i4; i += 4) {
            int s0 = __shfl_sync(0xffffffffu, sreg, i);
            int s1 = __shfl_sync(0xffffffffu, sreg, i + 1);
            int s2 = __shfl_sync(0xffffffffu, sreg, i + 2);
            int s3 = __shfl_sync(0xffffffffu, sreg, i + 3);
            float4 v0 = __ldg(x4 + (long long)s0 * 32 + lane);
            float4 v1 = __ldg(x4 + (long long)s1 * 32 + lane);
            float4 v2 = __ldg(x4 + (long long)s2 * 32 + lane);
            float4 v3 = __ldg(x4 + (long long)s3 * 32 + lane);
            a0.x += v0.x; a0.y += v0.y; a0.z += v0.z; a0.w += v0.w;
            a1.x += v1.x; a1.y += v1.y; a1.z += v1.z; a1.w += v1.w;
            a2.x += v2.x; a2.y += v2.y; a2.z += v2.z; a2.w += v2.w;
            a3.x += v3.x; a3.y += v3.y; a3.z += v3.z; a3.w += v3.w;
        }
        for (; i < cnt; i++) {
            int si = __shfl_sync(0xffffffffu, sreg, i);
            float4 v = __ldg(x4 + (long long)si * 32 + lane);
            a0.x += v.x; a0.y += v.y; a0.z += v.z; a0.w += v.w;
        }
    }
    float sc = invdeg[warp];
    float4 acc;
    acc.x = (a0.x + a1.x + a2.x + a3.x) * sc;
    acc.y = (a0.y + a1.y + a2.y + a3.y) * sc;
    acc.z = (a0.z + a1.z + a2.z + a3.z) * sc;
    acc.w = (a0.w + a1.w + a2.w + a3.w) * sc;
    __nv_bfloat16 h0, l0, h1, l1, h2, l2, h3, l3;
    split_bf16(acc.x, h0, l0); split_bf16(acc.y, h1, l1);
    split_bf16(acc.z, h2, l2); split_bf16(acc.w, h3, l3);
    long long rb = (long long)warp * ROWU32;
    int p0 = permk2(2 * lane);
    int p1 = permk2(2 * lane + 1);
    Ahi[rb + p0] = pack_bf16(h0, h1);
    Ahi[rb + p1] = pack_bf16(h2, h3);
    Alo[rb + p0] = pack_bf16(l0, l1);
    Alo[rb + p1] = pack_bf16(l2, l3);
}

// ---------------------------------------------------------------------------
// 3-term bf16 mma.sync GEMM + bias + ReLU + next-layer x-half split.
// CTA 128x128, warp 32x64, K=256 (128 k2) in 8 chunks, cp.async double-buffer.
// Permuted smem layout -> every fragment pair is one LDS.64; SAP=24 rows are
// conflict-free per half-warp phase. launch_bounds(256,1): no register spills.
// ---------------------------------------------------------------------------
#define SAP 24                        // uint32 row stride (16 used)
#define ARR_SZ (128 * SAP)            // 3072 uint32 = 12288 B
#define BUF_SZ (4 * ARR_SZ)           // Ah|Al|Bh|Bl
#define GEMM_SMEM (2 * BUF_SZ * 4)    // 98304 B

__global__ __launch_bounds__(256, 1)
void gemm_relu_kernel(const uint32_t* __restrict__ Ahi,
                      const uint32_t* __restrict__ Alo,
                      const uint32_t* __restrict__ Whi,
                      const uint32_t* __restrict__ Wlo,
                      const float* __restrict__ bl,
                      float* __restrict__ xout,
                      uint32_t* __restrict__ XhiOut,
                      uint32_t* __restrict__ XloOut,
                      int last) {
    extern __shared__ uint32_t smem[];
    const uint32_t sbase = smem_u32(smem);
    const int t = threadIdx.x;
    const int lane = t & 31;
    const int w = t >> 5;
    const int wr = (w >> 1) * 32;     // warp row offset
    const int wc = (w & 1) * 64;      // warp col offset
    const int qr = lane >> 2;
    const int qc = lane & 3;
    const int row0 = blockIdx.x * 128;

    float c[2][8][4];
#pragma unroll
    for (int ma = 0; ma < 2; ma++)
#pragma unroll
        for (int na = 0; na < 8; na++)
#pragma unroll
            for (int q = 0; q < 4; q++) c[ma][na][q] = 0.0f;

    auto load_chunk = [&](int i, int b) {
        uint32_t bb = sbase + (uint32_t)(b * BUF_SZ * 4);
#pragma unroll
        for (int s = 0; s < 8; s++) {
            int slot = t + s * 256;
            int arr = slot >> 9;
            int rem = slot & 511;
            int r = rem >> 2;
            int g = rem & 3;
            uint32_t saddr = bb + (uint32_t)(arr * ARR_SZ * 4 + r * (SAP * 4) + g * 16);
            const uint32_t* gp;
            if (arr < 2) {
                int rg = row0 + r;
                if (rg >= N_NODES) rg = N_NODES - 1;
                const uint32_t* basep = arr == 0 ? Ahi : Alo;
                gp = basep + (long long)rg * ROWU32 + i * 16 + g * 4;
            } else {
                const uint32_t* basep = arr == 2 ? Whi : Wlo;
                gp = basep + r * ROWU32 + i * 16 + g * 4;
            }
            cp16(saddr, gp);
        }
        CP_COMMIT();
    };

    load_chunk(0, 0);

    for (int i = 0; i < 8; i++) {
        const int b = i & 1;
        if (i < 7) load_chunk(i + 1, b ^ 1);
        if (i < 7) CP_WAIT(1); else CP_WAIT(0);
        __syncthreads();

        const uint32_t* Ah = smem + b * BUF_SZ;
        const uint32_t* Al = Ah + ARR_SZ;
        const uint32_t* Bh = Al + ARR_SZ;
        const uint32_t* Bl = Bh + ARR_SZ;

#pragma unroll
        for (int ks = 0; ks < 2; ks++) {
            uint2 ahp[2][2], alp[2][2];
#pragma unroll
            for (int ma = 0; ma < 2; ma++) {
                int ro = (wr + ma * 16 + qr) * SAP + ks * 8 + 2 * qc;
                ahp[ma][0] = *(const uint2*)(Ah + ro);
                ahp[ma][1] = *(const uint2*)(Ah + ro + 8 * SAP);
                alp[ma][0] = *(const uint2*)(Al + ro);
                alp[ma][1] = *(const uint2*)(Al + ro + 8 * SAP);
            }
#pragma unroll
            for (int na = 0; na < 8; na++) {
                int bo = (wc + na * 8 + qr) * SAP + ks * 8 + 2 * qc;
                uint2 bh = *(const uint2*)(Bh + bo);
                uint2 bv = *(const uint2*)(Bl + bo);
#pragma unroll
                for (int ma = 0; ma < 2; ma++) {
                    uint32_t ah[4] = {ahp[ma][0].x, ahp[ma][1].x,
                                      ahp[ma][0].y, ahp[ma][1].y};
                    uint32_t al[4] = {alp[ma][0].x, alp[ma][1].x,
                                      alp[ma][0].y, alp[ma][1].y};
                    mma_bf16(c[ma][na], ah, bh.x, bh.y);  // hi*hi
                    mma_bf16(c[ma][na], ah, bv.x, bv.y);  // hi*lo
                    mma_bf16(c[ma][na], al, bh.x, bh.y);  // lo*hi
                }
            }
        }
        __syncthreads();
    }

    // ---- epilogue: bias + relu + fp32 store + next-layer x-half split ----
#pragma unroll
    for (int na = 0; na < 8; na++) {
        int col = wc + na * 8 + 2 * qc;
        float b0 = __ldg(bl + col), b1 = __ldg(bl + col + 1);
        int k2 = 64 + (col >> 1);
        int pidx = permk2(k2);
#pragma unroll
        for (int ma = 0; ma < 2; ma++) {
            int r0 = row0 + wr + ma * 16 + qr;
            int r1 = r0 + 8;
            float ox0 = fmaxf(c[ma][na][0] + b0, 0.f);
            float oy0 = fmaxf(c[ma][na][1] + b1, 0.f);
            float ox1 = fmaxf(c[ma][na][2] + b0, 0.f);
            float oy1 = fmaxf(c[ma][na][3] + b1, 0.f);
            if (r0 < N_NODES) {
                *(float2*)(xout + (long long)r0 * D + col) = make_float2(ox0, oy0);
                if (!last) {
                    __nv_bfloat16 h0, l0, h1, l1;
                    split_bf16(ox0, h0, l0);
                    split_bf16(oy0, h1, l1);
                    XhiOut[(long long)r0 * ROWU32 + pidx] = pack_bf16(h0, h1);
                    XloOut[(long long)r0 * ROWU32 + pidx] = pack_bf16(l0, l1);
                }
            }
            if (r1 < N_NODES) {
                *(float2*)(xout + (long long)r1 * D + col) = make_float2(ox1, oy1);
                if (!last) {
                    __nv_bfloat16 h0, l0, h1, l1;
                    split_bf16(ox1, h0, l0);
                    split_bf16(oy1, h1, l1);
                    XhiOut[(long long)r1 * ROWU32 + pidx] = pack_bf16(h0, h1);
                    XloOut[(long long)r1 * ROWU32 + pidx] = pack_bf16(l0, l1);
                }
            }
        }
    }
}

// ---------------------------------------------------------------------------
// kernel_launch
// ---------------------------------------------------------------------------
extern "C" void kernel_launch(void* const* d_in, const int* in_sizes, int n_in,
                              void* d_out, int out_size) {
    const float* x  = (const float*)d_in[0];
    const int*   ei = (const int*)  d_in[1];
    const float* Wl = (const float*)d_in[2];
    const float* bl = (const float*)d_in[3];
    const float* Wr = (const float*)d_in[4];
    float* out = (float*)d_out;

    const int* src = ei;
    const int* dst = ei + N_EDGES;

    float *bufA, *bufB, *invdeg;
    int *deg, *cursor, *rowstart, *csr_src;
    uint32_t *ahi, *alo, *whi, *wlo;
    cudaGetSymbolAddress((void**)&bufA,     g_bufA);
    cudaGetSymbolAddress((void**)&bufB,     g_bufB);
    cudaGetSymbolAddress((void**)&invdeg,   g_invdeg);
    cudaGetSymbolAddress((void**)&deg,      g_deg);
    cudaGetSymbolAddress((void**)&cursor,   g_cursor);
    cudaGetSymbolAddress((void**)&rowstart, g_rowstart);
    cudaGetSymbolAddress((void**)&csr_src,  g_csr_src);
    cudaGetSymbolAddress((void**)&ahi,      g_Ahi);
    cudaGetSymbolAddress((void**)&alo,      g_Alo);
    cudaGetSymbolAddress((void**)&whi,      g_Whi);
    cudaGetSymbolAddress((void**)&wlo,      g_Wlo);

    cudaFuncSetAttribute(gemm_relu_kernel,
                         cudaFuncAttributeMaxDynamicSharedMemorySize, GEMM_SMEM);

    zero_kernel<<<(N_NODES + 255) / 256, 256>>>(deg);                    // #1
    deg_kernel<<<(N_EDGES + 255) / 256, 256>>>(dst, deg);                // #2
    scan_kernel<<<1, 1024>>>(deg, rowstart, invdeg, cursor);             // #3
    fill_kernel<<<(N_NODES * 64 + 255) / 256, 256>>>(src, dst, rowstart, // #4
                                                     cursor, csr_src,
                                                     Wl, Wr, x,
                                                     whi, wlo, ahi, alo);

    const int gather_blocks = (N_NODES * 32 + 255) / 256;
    const int gemm_blocks = (N_NODES + 127) / 128;

    const float* cur = x;
    float* outs[N_LAYERS] = {bufA, bufB, bufA, out};

    for (int l = 0; l < N_LAYERS; l++) {
        gather_kernel<<<gather_blocks, 256>>>((const float4*)cur, csr_src,   // #5
                                              rowstart, invdeg, ahi, alo);
        gemm_relu_kernel<<<gemm_blocks, 256, GEMM_SMEM>>>(                   // #6
            ahi, alo,
            whi + (size_t)l * D * ROWU32,
            wlo + (size_t)l * D * ROWU32,
            bl + (size_t)l * D,
            outs[l], ahi, alo, (l == N_LAYERS - 1) ? 1 : 0);
        cur = outs[l];
    }
}

// round 10
// speedup vs baseline: 1.1290x; 1.1290x over previous
#include <cuda_runtime.h>
#include <cuda_bf16.h>
#include <cstdint>

#define N_NODES 100000
#define N_EDGES 1600000
#define D 128
#define N_LAYERS 4
#define ROWU32 128          // 256 bf16 per activation row = 128 uint32

// ---------------- scratch (__device__ globals; no allocation) ----------------
__device__ float g_bufA[N_NODES * D];
__device__ float g_bufB[N_NODES * D];
__device__ float g_invdeg[N_NODES];
__device__ int   g_deg[N_NODES];
__device__ int   g_cursor[N_NODES];
__device__ int   g_rowstart[N_NODES + 1];
__device__ int   g_csr_src[N_EDGES];
// Packed bf16 activations [row][k2 permuted]: k2<64 = agg-half, >=64 = x-half
__device__ uint32_t g_Ahi[(size_t)N_NODES * ROWU32];
__device__ uint32_t g_Alo[(size_t)N_NODES * ROWU32];
// Packed bf16 weights [l][j][k2 permuted] (k<128 -> Wl, k>=128 -> Wr)
__device__ uint32_t g_Whi[N_LAYERS * D * ROWU32];
__device__ uint32_t g_Wlo[N_LAYERS * D * ROWU32];

// ------------------------------ helpers -------------------------------------
__device__ __forceinline__ uint32_t smem_u32(const void* p) {
    uint32_t a;
    asm("{ .reg .u64 t; cvta.to.shared.u64 t, %1; cvt.u32.u64 %0, t; }"
        : "=r"(a) : "l"(p));
    return a;
}
__device__ __forceinline__ void cp16(uint32_t saddr, const void* g) {
    asm volatile("cp.async.ca.shared.global [%0], [%1], 16;"
                 :: "r"(saddr), "l"(g) : "memory");
}
#define CP_COMMIT() asm volatile("cp.async.commit_group;" ::: "memory")
#define CP_WAIT(n)  asm volatile("cp.async.wait_group %0;" :: "n"(n) : "memory")

__device__ __forceinline__ uint32_t pack_bf16(__nv_bfloat16 a, __nv_bfloat16 b) {
    return ((uint32_t)__bfloat16_as_ushort(b) << 16) | (uint32_t)__bfloat16_as_ushort(a);
}
__device__ __forceinline__ void split_bf16(float x, __nv_bfloat16& h, __nv_bfloat16& l) {
    h = __float2bfloat16(x);
    l = __float2bfloat16(x - __bfloat162float(h));
}
// column permutation: within each 16-k2 chunk, pairs (c, c+4) become adjacent
__device__ __forceinline__ int permk2(int k2) {
    int c = k2 & 15;
    return (k2 & ~15) | ((c & 3) << 1) | ((c >> 2) & 1) | (c & 8);
}

__device__ __forceinline__ void mma_bf16(float c[4], const uint32_t a[4],
                                         uint32_t b0, uint32_t b1) {
    asm volatile(
        "mma.sync.aligned.m16n8k16.row.col.f32.bf16.bf16.f32 "
        "{%0,%1,%2,%3}, {%4,%5,%6,%7}, {%8,%9}, {%0,%1,%2,%3};"
        : "+f"(c[0]), "+f"(c[1]), "+f"(c[2]), "+f"(c[3])
        : "r"(a[0]), "r"(a[1]), "r"(a[2]), "r"(a[3]), "r"(b0), "r"(b1));
}

// ---------------------------------------------------------------------------
// Setup kernels
// ---------------------------------------------------------------------------
__global__ void deg_kernel(const int* __restrict__ dst, int* __restrict__ deg) {
    int e = blockIdx.x * blockDim.x + threadIdx.x;
    if (e < N_EDGES) atomicAdd(&deg[dst[e]], 1);
}

// scan also zeroes cursor (fill runs after)
__global__ void scan_kernel(const int* __restrict__ deg,
                            int* __restrict__ row_start,
                            float* __restrict__ invdeg,
                            int* __restrict__ cursor) {
    __shared__ int sm[1024];
    const int t = threadIdx.x;
    const int CH = (N_NODES + 1023) / 1024;
    const int base = t * CH;
    int s = 0;
    for (int i = 0; i < CH; i++) {
        int idx = base + i;
        if (idx < N_NODES) s += deg[idx];
    }
    sm[t] = s;
    __syncthreads();
    for (int d = 1; d < 1024; d <<= 1) {
        int v = (t >= d) ? sm[t - d] : 0;
        __syncthreads();
        sm[t] += v;
        __syncthreads();
    }
    int off = sm[t] - s;
    for (int i = 0; i < CH; i++) {
        int idx = base + i;
        if (idx < N_NODES) {
            row_start[idx] = off;
            int dg = deg[idx];
            off += dg;
            invdeg[idx] = 1.0f / fmaxf((float)dg, 1.0f);
            cursor[idx] = 0;
        }
    }
    if (t == 1023) row_start[N_NODES] = off;
}

// fill: CSR fill + permuted W hi/lo split
__global__ void fill_kernel(const int* __restrict__ src,
                            const int* __restrict__ dst,
                            const int* __restrict__ row_start,
                            int* __restrict__ cursor,
                            int* __restrict__ csr_src,
                            const float* __restrict__ Wl,
                            const float* __restrict__ Wr,
                            uint32_t* __restrict__ Whi,
                            uint32_t* __restrict__ Wlo) {
    int e = blockIdx.x * blockDim.x + threadIdx.x;
    if (e < N_EDGES) {
        int d = dst[e];
        int p = atomicAdd(&cursor[d], 1);
        csr_src[row_start[d] + p] = src[e];
    }
    if (e < N_LAYERS * D * ROWU32) {
        int k2 = e & (ROWU32 - 1);
        int j  = (e >> 7) & (D - 1);
        int l  = e >> 14;
        int k0 = 2 * k2, k1 = 2 * k2 + 1;
        float w0 = (k0 < D) ? Wl[(l * D + j) * D + k0] : Wr[(l * D + j) * D + (k0 - D)];
        float w1 = (k1 < D) ? Wl[(l * D + j) * D + k1] : Wr[(l * D + j) * D + (k1 - D)];
        __nv_bfloat16 h0, l0, h1, l1;
        split_bf16(w0, h0, l0);
        split_bf16(w1, h1, l1);
        int idx = (l * D + j) * ROWU32 + permk2(k2);
        Whi[idx] = pack_bf16(h0, h1);
        Wlo[idx] = pack_bf16(l0, l1);
    }
}

// ---------------------------------------------------------------------------
// Gather-mean -> packed bf16 hi/lo agg-half; also splits own x row (x-half).
// Exact R8 loop structure (proven 62.7us) with permuted store indices.
// ---------------------------------------------------------------------------
__global__ __launch_bounds__(256)
void gather_kernel(const float4* __restrict__ x4,
                   const int* __restrict__ csr_src,
                   const int* __restrict__ row_start,
                   const float* __restrict__ invdeg,
                   uint32_t* __restrict__ Ahi,
                   uint32_t* __restrict__ Alo) {
    int warp = (blockIdx.x * blockDim.x + threadIdx.x) >> 5;
    int lane = threadIdx.x & 31;
    if (warp >= N_NODES) return;
    int b = row_start[warp];
    int e = row_start[warp + 1];
    float4 acc = make_float4(0.f, 0.f, 0.f, 0.f);
    for (int j = b; j < e; j += 32) {
        int cnt = min(32, e - j);
        int sreg = (lane < cnt) ? csr_src[j + lane] : 0;
        for (int i = 0; i < cnt; i++) {
            int si = __shfl_sync(0xffffffffu, sreg, i);
            float4 v = __ldg(x4 + (long long)si * 32 + lane);
            acc.x += v.x; acc.y += v.y; acc.z += v.z; acc.w += v.w;
        }
    }
    float sc = invdeg[warp];
    acc.x *= sc; acc.y *= sc; acc.z *= sc; acc.w *= sc;
    long long rb = (long long)warp * ROWU32;
    __nv_bfloat16 h0, l0, h1, l1, h2, l2, h3, l3;
    split_bf16(acc.x, h0, l0); split_bf16(acc.y, h1, l1);
    split_bf16(acc.z, h2, l2); split_bf16(acc.w, h3, l3);
    int p0 = permk2(2 * lane), p1 = permk2(2 * lane + 1);
    Ahi[rb + p0] = pack_bf16(h0, h1);
    Ahi[rb + p1] = pack_bf16(h2, h3);
    Alo[rb + p0] = pack_bf16(l0, l1);
    Alo[rb + p1] = pack_bf16(l2, l3);
    // own x row -> x-half
    float4 mine = __ldg(x4 + (long long)warp * 32 + lane);
    split_bf16(mine.x, h0, l0); split_bf16(mine.y, h1, l1);
    split_bf16(mine.z, h2, l2); split_bf16(mine.w, h3, l3);
    int q0 = permk2(64 + 2 * lane), q1 = permk2(64 + 2 * lane + 1);
    Ahi[rb + q0] = pack_bf16(h0, h1);
    Ahi[rb + q1] = pack_bf16(h2, h3);
    Alo[rb + q0] = pack_bf16(l0, l1);
    Alo[rb + q1] = pack_bf16(l2, l3);
}

// ---------------------------------------------------------------------------
// 3-term bf16 mma.sync GEMM + bias + ReLU.
// CTA tile 64(M) x 64(N), 128 threads (4 warps, each 32x32). K=256 (128 k2)
// in 8 chunks of 16 k2, cp.async double-buffered. Permuted layout -> LDS.64
// fragment loads; SAP=24 conflict-free. 32 accum regs -> no spills; 48KB smem
// -> 4 CTAs/SM (16 warps/SM).
// ---------------------------------------------------------------------------
#define SAP 24                        // uint32 row stride (16 used)
#define ARR_SZ (64 * SAP)             // 1536 u32 = 6144 B per operand array
#define BUF_SZ (4 * ARR_SZ)           // Ah|Al|Bh|Bl = 24576 B
#define GEMM_SMEM (2 * BUF_SZ * 4)    // 49152 B

__global__ __launch_bounds__(128, 4)
void gemm_relu_kernel(const uint32_t* __restrict__ Ahi,
                      const uint32_t* __restrict__ Alo,
                      const uint32_t* __restrict__ Whi,
                      const uint32_t* __restrict__ Wlo,
                      const float* __restrict__ bl,
                      float* __restrict__ xout) {
    extern __shared__ uint32_t smem[];
    const uint32_t sbase = smem_u32(smem);
    const int t = threadIdx.x;
    const int lane = t & 31;
    const int w = t >> 5;
    const int wr = (w >> 1) * 32;     // warp row offset in 64-row tile
    const int wc = (w & 1) * 32;      // warp col offset in 64-col tile
    const int qr = lane >> 2;
    const int qc = lane & 3;
    const int row0 = blockIdx.x * 64;
    const int col0 = blockIdx.y * 64; // which half of the 128 output cols

    float c[2][4][4];
#pragma unroll
    for (int ma = 0; ma < 2; ma++)
#pragma unroll
        for (int na = 0; na < 4; na++)
#pragma unroll
            for (int q = 0; q < 4; q++) c[ma][na][q] = 0.0f;

    auto load_chunk = [&](int i, int b) {
        uint32_t bb = sbase + (uint32_t)(b * BUF_SZ * 4);
#pragma unroll
        for (int s = 0; s < 8; s++) {
            int slot = t + s * 128;       // 0..1023
            int arr = slot >> 8;          // 0..3
            int rem = slot & 255;
            int r = rem >> 2;             // 0..63
            int g = rem & 3;
            uint32_t saddr = bb + (uint32_t)(arr * ARR_SZ * 4 + r * (SAP * 4) + g * 16);
            const uint32_t* gp;
            if (arr < 2) {
                int rg = row0 + r;
                if (rg >= N_NODES) rg = N_NODES - 1;
                const uint32_t* basep = arr == 0 ? Ahi : Alo;
                gp = basep + (long long)rg * ROWU32 + i * 16 + g * 4;
            } else {
                const uint32_t* basep = arr == 2 ? Whi : Wlo;
                gp = basep + (col0 + r) * ROWU32 + i * 16 + g * 4;
            }
            cp16(saddr, gp);
        }
        CP_COMMIT();
    };

    load_chunk(0, 0);

    for (int i = 0; i < 8; i++) {
        const int b = i & 1;
        if (i < 7) load_chunk(i + 1, b ^ 1);
        if (i < 7) CP_WAIT(1); else CP_WAIT(0);
        __syncthreads();

        const uint32_t* Ah = smem + b * BUF_SZ;
        const uint32_t* Al = Ah + ARR_SZ;
        const uint32_t* Bh = Al + ARR_SZ;
        const uint32_t* Bl = Bh + ARR_SZ;

#pragma unroll
        for (int ks = 0; ks < 2; ks++) {
            uint2 ahp[2][2], alp[2][2];
#pragma unroll
            for (int ma = 0; ma < 2; ma++) {
                int ro = (wr + ma * 16 + qr) * SAP + ks * 8 + 2 * qc;
                ahp[ma][0] = *(const uint2*)(Ah + ro);
                ahp[ma][1] = *(const uint2*)(Ah + ro + 8 * SAP);
                alp[ma][0] = *(const uint2*)(Al + ro);
                alp[ma][1] = *(const uint2*)(Al + ro + 8 * SAP);
            }
#pragma unroll
            for (int na = 0; na < 4; na++) {
                int bo = (wc + na * 8 + qr) * SAP + ks * 8 + 2 * qc;
                uint2 bh = *(const uint2*)(Bh + bo);
                uint2 bv = *(const uint2*)(Bl + bo);
#pragma unroll
                for (int ma = 0; ma < 2; ma++) {
                    uint32_t ah[4] = {ahp[ma][0].x, ahp[ma][1].x,
                                      ahp[ma][0].y, ahp[ma][1].y};
                    uint32_t al[4] = {alp[ma][0].x, alp[ma][1].x,
                                      alp[ma][0].y, alp[ma][1].y};
                    mma_bf16(c[ma][na], ah, bh.x, bh.y);  // hi*hi
                    mma_bf16(c[ma][na], ah, bv.x, bv.y);  // hi*lo
                    mma_bf16(c[ma][na], al, bh.x, bh.y);  // lo*hi
                }
            }
        }
        __syncthreads();
    }

    // ---- epilogue: bias + relu + fp32 store ----
#pragma unroll
    for (int na = 0; na < 4; na++) {
        int col = col0 + wc + na * 8 + 2 * qc;
        float b0 = __ldg(bl + col), b1 = __ldg(bl + col + 1);
#pragma unroll
        for (int ma = 0; ma < 2; ma++) {
            int r0 = row0 + wr + ma * 16 + qr;
            int r1 = r0 + 8;
            if (r0 < N_NODES) {
                float2 o;
                o.x = fmaxf(c[ma][na][0] + b0, 0.f);
                o.y = fmaxf(c[ma][na][1] + b1, 0.f);
                *(float2*)(xout + (long long)r0 * D + col) = o;
            }
            if (r1 < N_NODES) {
                float2 o;
                o.x = fmaxf(c[ma][na][2] + b0, 0.f);
                o.y = fmaxf(c[ma][na][3] + b1, 0.f);
                *(float2*)(xout + (long long)r1 * D + col) = o;
            }
        }
    }
}

// ---------------------------------------------------------------------------
// kernel_launch
// ---------------------------------------------------------------------------
extern "C" void kernel_launch(void* const* d_in, const int* in_sizes, int n_in,
                              void* d_out, int out_size) {
    const float* x  = (const float*)d_in[0];
    const int*   ei = (const int*)  d_in[1];
    const float* Wl = (const float*)d_in[2];
    const float* bl = (const float*)d_in[3];
    const float* Wr = (const float*)d_in[4];
    float* out = (float*)d_out;

    const int* src = ei;
    const int* dst = ei + N_EDGES;

    float *bufA, *bufB, *invdeg;
    int *deg, *cursor, *rowstart, *csr_src;
    uint32_t *ahi, *alo, *whi, *wlo;
    cudaGetSymbolAddress((void**)&bufA,     g_bufA);
    cudaGetSymbolAddress((void**)&bufB,     g_bufB);
    cudaGetSymbolAddress((void**)&invdeg,   g_invdeg);
    cudaGetSymbolAddress((void**)&deg,      g_deg);
    cudaGetSymbolAddress((void**)&cursor,   g_cursor);
    cudaGetSymbolAddress((void**)&rowstart, g_rowstart);
    cudaGetSymbolAddress((void**)&csr_src,  g_csr_src);
    cudaGetSymbolAddress((void**)&ahi,      g_Ahi);
    cudaGetSymbolAddress((void**)&alo,      g_Alo);
    cudaGetSymbolAddress((void**)&whi,      g_Whi);
    cudaGetSymbolAddress((void**)&wlo,      g_Wlo);

    cudaFuncSetAttribute(gemm_relu_kernel,
                         cudaFuncAttributeMaxDynamicSharedMemorySize, GEMM_SMEM);

    cudaMemsetAsync(deg, 0, N_NODES * sizeof(int));
    deg_kernel<<<(N_EDGES + 255) / 256, 256>>>(dst, deg);
    scan_kernel<<<1, 1024>>>(deg, rowstart, invdeg, cursor);
    fill_kernel<<<(N_EDGES + 255) / 256, 256>>>(src, dst, rowstart,
                                                cursor, csr_src,
                                                Wl, Wr, whi, wlo);

    const int gather_blocks = (N_NODES * 32 + 255) / 256;
    const dim3 gemm_grid((N_NODES + 63) / 64, 2);

    const float* cur = x;
    float* outs[N_LAYERS] = {bufA, bufB, bufA, out};

    for (int l = 0; l < N_LAYERS; l++) {
        gather_kernel<<<gather_blocks, 256>>>((const float4*)cur, csr_src,
                                              rowstart, invdeg, ahi, alo);
        gemm_relu_kernel<<<gemm_grid, 128, GEMM_SMEM>>>(
            ahi, alo,
            whi + (size_t)l * D * ROWU32,
            wlo + (size_t)l * D * ROWU32,
            bl + (size_t)l * D,
            outs[l]);
        cur = outs[l];
    }
}